// round 7
// baseline (speedup 1.0000x reference)
#include <cuda_runtime.h>

#define N_NODES   100000
#define N_EDGES   1600000
#define D_FEAT    64
#define F4_PER_ROW (D_FEAT / 4)       // 16
#define CAP       64                  // per-node bucket capacity (P(overflow) ~ 4e-13)

// -------- scratch (static __device__; no allocation) --------
// g_cnt is zero at load; each replay's aggregate re-zeroes it for the next.
__device__ int g_cnt[N_NODES];
__device__ int g_bucket[N_NODES * CAP];       // 25.6 MB; only [0, cnt) read back

// -------- build: one atomic pass, no scan, contiguous output --------
__global__ void k_build(const int* __restrict__ edge_index, int E) {
    int e = blockIdx.x * blockDim.x + threadIdx.x;
    if (e >= E) return;
    int s = __ldg(&edge_index[e]);            // src
    int d = __ldg(&edge_index[E + e]);        // dst
    int pos = atomicAdd(&g_cnt[d], 1);
    if (pos < CAP)                            // deterministically true for this data
        g_bucket[d * CAP + pos] = s;
}

__device__ __forceinline__ float4 fmax4(float4 a, float4 b) {
    a.x = fmaxf(a.x, b.x); a.y = fmaxf(a.y, b.y);
    a.z = fmaxf(a.z, b.z); a.w = fmaxf(a.w, b.w);
    return a;
}

// One warp per node; half-warp per row; 4 rows per iteration via 4 LDG.128.
// Out-of-range indices clamp to last (duplicate under max = no-op).
// Lane 0 reads-then-zeroes this node's counter (next-replay housekeeping).
__global__ void k_aggregate(const float* __restrict__ h,
                            float* __restrict__ out, int n) {
    int warp = (blockIdx.x * blockDim.x + threadIdx.x) >> 5;
    int lane = threadIdx.x & 31;
    if (warp >= n) return;

    int cnt;
    if (lane == 0) {
        cnt = __ldcg(&g_cnt[warp]);
        __stcg(&g_cnt[warp], 0);              // reset for next replay
    }
    cnt = __shfl_sync(0xffffffffu, cnt, 0);
    cnt = min(cnt, CAP);

    int start = warp * CAP;
    int end   = start + cnt;
    int hw = lane >> 4;
    int fl = lane & 15;

    const float NEG_INF = __int_as_float(0xff800000);
    float4 acc = make_float4(NEG_INF, NEG_INF, NEG_INF, NEG_INF);

    const float4* __restrict__ h4 = reinterpret_cast<const float4*>(h);

    for (int base = start; base < end; base += 8) {
        int e1 = end - 1;
        int i0 = min(base +     hw, e1);
        int i1 = min(base + 2 + hw, e1);
        int i2 = min(base + 4 + hw, e1);
        int i3 = min(base + 6 + hw, e1);
        int s0 = __ldg(&g_bucket[i0]);
        int s1 = __ldg(&g_bucket[i1]);
        int s2 = __ldg(&g_bucket[i2]);
        int s3 = __ldg(&g_bucket[i3]);
        float4 v0 = __ldg(&h4[s0 * F4_PER_ROW + fl]);
        float4 v1 = __ldg(&h4[s1 * F4_PER_ROW + fl]);
        float4 v2 = __ldg(&h4[s2 * F4_PER_ROW + fl]);
        float4 v3 = __ldg(&h4[s3 * F4_PER_ROW + fl]);
        acc = fmax4(acc, fmax4(fmax4(v0, v1), fmax4(v2, v3)));
    }

    acc.x = fmaxf(acc.x, __shfl_xor_sync(0xffffffffu, acc.x, 16));
    acc.y = fmaxf(acc.y, __shfl_xor_sync(0xffffffffu, acc.y, 16));
    acc.z = fmaxf(acc.z, __shfl_xor_sync(0xffffffffu, acc.z, 16));
    acc.w = fmaxf(acc.w, __shfl_xor_sync(0xffffffffu, acc.w, 16));

    if (cnt == 0) acc = make_float4(0.f, 0.f, 0.f, 0.f);

    if (lane < 16)
        reinterpret_cast<float4*>(out)[warp * F4_PER_ROW + fl] = acc;
}

// -------- launch: exactly two graph nodes, no memsets --------
extern "C" void kernel_launch(void* const* d_in, const int* in_sizes, int n_in,
                              void* d_out, int out_size) {
    const float* h = (const float*)d_in[0];
    const int* edge_index = (const int*)d_in[1];
    float* out = (float*)d_out;

    const int N = in_sizes[0] / D_FEAT;      // 100000
    const int E = in_sizes[1] / 2;           // 1600000

    const int T = 256;
    k_build<<<(E + T - 1) / T, T>>>(edge_index, E);

    int blocks = (N * 32 + T - 1) / T;       // 12500
    k_aggregate<<<blocks, T>>>(h, out, N);
}

// round 8
// speedup vs baseline: 1.9317x; 1.9317x over previous
#include <cuda_runtime.h>

#define N_NODES   100000
#define N_EDGES   1600000
#define D_FEAT    64
#define F4_PER_ROW (D_FEAT / 4)       // 16
#define CAP       64                  // bucket capacity; P(deg>64) ~ 4e-13 overall

// -------- scratch (static __device__; no allocation) --------
__device__ int4 g_bucket4[N_NODES * (CAP / 4)];  // 25.6 MB staging (int view in build)
__device__ int  g_cnt[N_NODES];                  // zero at load; reset by k_compact
__device__ int  g_csr[N_EDGES];                  // dense 6.4 MB index list
__device__ int2 g_span[N_NODES];                 // (start, cnt) per node
__device__ int  g_total;                         // global cursor; reset by aggregate

// -------- build: one atomic per edge, scattered bucket write --------
__global__ void k_build(const int* __restrict__ edge_index, int E) {
    int e = blockIdx.x * blockDim.x + threadIdx.x;
    if (e >= E) return;
    int s = __ldg(&edge_index[e]);
    int d = __ldg(&edge_index[E + e]);
    int pos = atomicAdd(&g_cnt[d], 1);
    if (pos < CAP)
        reinterpret_cast<int*>(g_bucket4)[d * CAP + pos] = s;
}

// -------- compact: bucket rows -> dense csr + spans --------
// One warp per node. Full-line bucket read (1 LDG.128/lane), block-aggregated
// span allocation (1 global atomic per block). Resets g_cnt for next replay.
__global__ void k_compact(int n) {
    __shared__ int s_warpoff[8];
    __shared__ int s_blocktotal;
    __shared__ int s_base;
    int gtid = blockIdx.x * blockDim.x + threadIdx.x;
    int warp = gtid >> 5;
    int lane = threadIdx.x & 31;
    int wloc = threadIdx.x >> 5;

    int cnt = 0;
    if (warp < n && lane == 0) {
        cnt = __ldcg(&g_cnt[warp]);
        __stcg(&g_cnt[warp], 0);            // reset for next replay
        cnt = min(cnt, CAP);
    }
    cnt = __shfl_sync(0xffffffffu, cnt, 0);

    if (threadIdx.x == 0) s_blocktotal = 0;
    __syncthreads();
    if (lane == 0) s_warpoff[wloc] = atomicAdd(&s_blocktotal, cnt);
    __syncthreads();
    if (threadIdx.x == 0) s_base = atomicAdd(&g_total, s_blocktotal);
    __syncthreads();

    if (warp >= n) return;
    int start = s_base + s_warpoff[wloc];

    if (lane == 0) g_span[warp] = make_int2(start, cnt);

    if (lane < 16) {
        int4 v = __ldg(&g_bucket4[warp * (CAP / 4) + lane]);
        int b = 4 * lane;
        if (b     < cnt) g_csr[start + b]     = v.x;
        if (b + 1 < cnt) g_csr[start + b + 1] = v.y;
        if (b + 2 < cnt) g_csr[start + b + 2] = v.z;
        if (b + 3 < cnt) g_csr[start + b + 3] = v.w;
    }
}

__device__ __forceinline__ float4 fmax4(float4 a, float4 b) {
    a.x = fmaxf(a.x, b.x); a.y = fmaxf(a.y, b.y);
    a.z = fmaxf(a.z, b.z); a.w = fmaxf(a.w, b.w);
    return a;
}

// One warp per node; half-warp per row; 4 rows/iter via 4 LDG.128 (R3 layout).
// Out-of-range indices clamp to end-1 (duplicate under max = no-op).
__global__ void k_aggregate(const float* __restrict__ h,
                            float* __restrict__ out, int n) {
    int gtid = blockIdx.x * blockDim.x + threadIdx.x;
    if (gtid == 0) g_total = 0;               // reset cursor for next replay

    int warp = gtid >> 5;
    int lane = threadIdx.x & 31;
    if (warp >= n) return;

    int2 span = __ldg(&g_span[warp]);
    int start = span.x;
    int end   = span.x + span.y;
    int hw = lane >> 4;
    int fl = lane & 15;

    const float NEG_INF = __int_as_float(0xff800000);
    float4 acc = make_float4(NEG_INF, NEG_INF, NEG_INF, NEG_INF);

    const float4* __restrict__ h4 = reinterpret_cast<const float4*>(h);

    for (int base = start; base < end; base += 8) {
        int e1 = end - 1;
        int i0 = min(base +     hw, e1);
        int i1 = min(base + 2 + hw, e1);
        int i2 = min(base + 4 + hw, e1);
        int i3 = min(base + 6 + hw, e1);
        int s0 = __ldg(&g_csr[i0]);
        int s1 = __ldg(&g_csr[i1]);
        int s2 = __ldg(&g_csr[i2]);
        int s3 = __ldg(&g_csr[i3]);
        float4 v0 = __ldg(&h4[s0 * F4_PER_ROW + fl]);
        float4 v1 = __ldg(&h4[s1 * F4_PER_ROW + fl]);
        float4 v2 = __ldg(&h4[s2 * F4_PER_ROW + fl]);
        float4 v3 = __ldg(&h4[s3 * F4_PER_ROW + fl]);
        acc = fmax4(acc, fmax4(fmax4(v0, v1), fmax4(v2, v3)));
    }

    acc.x = fmaxf(acc.x, __shfl_xor_sync(0xffffffffu, acc.x, 16));
    acc.y = fmaxf(acc.y, __shfl_xor_sync(0xffffffffu, acc.y, 16));
    acc.z = fmaxf(acc.z, __shfl_xor_sync(0xffffffffu, acc.z, 16));
    acc.w = fmaxf(acc.w, __shfl_xor_sync(0xffffffffu, acc.w, 16));

    if (span.y == 0) acc = make_float4(0.f, 0.f, 0.f, 0.f);

    if (lane < 16)
        reinterpret_cast<float4*>(out)[warp * F4_PER_ROW + fl] = acc;
}

// -------- launch: three graph nodes, no memsets --------
extern "C" void kernel_launch(void* const* d_in, const int* in_sizes, int n_in,
                              void* d_out, int out_size) {
    const float* h = (const float*)d_in[0];
    const int* edge_index = (const int*)d_in[1];
    float* out = (float*)d_out;

    const int N = in_sizes[0] / D_FEAT;      // 100000
    const int E = in_sizes[1] / 2;           // 1600000

    const int T = 256;
    k_build<<<(E + T - 1) / T, T>>>(edge_index, E);

    int blocks = (N * 32 + T - 1) / T;       // 12500
    k_compact<<<blocks, T>>>(N);
    k_aggregate<<<blocks, T>>>(h, out, N);
}

// round 10
// speedup vs baseline: 4.2254x; 2.1874x over previous
#include <cuda_runtime.h>

#define N_NODES   100000
#define N_EDGES   1600000
#define D_FEAT    64
#define F4_PER_ROW (D_FEAT / 4)       // 16
#define NCHAIN    4                   // chains per node; half-warp chases 2, interleaved

// -------- scratch (static __device__; no allocation) --------
__device__ int  g_head[NCHAIN * N_NODES];     // 1.6 MB; memset to 0xFF each call
__device__ int2 g_link[N_EDGES];              // (next_edge, src_node), 12.8 MB

// -------- build: one atomicExch per edge, coalesced link store --------
__global__ void k_build(const int* __restrict__ edge_index, int E) {
    int e = blockIdx.x * blockDim.x + threadIdx.x;
    if (e >= E) return;
    int s = __ldg(&edge_index[e]);            // src
    int d = __ldg(&edge_index[E + e]);        // dst
    int bucket = NCHAIN * d + (e & (NCHAIN - 1));
    int old = atomicExch(&g_head[bucket], e);
    g_link[e] = make_int2(old, s);
}

__device__ __forceinline__ float4 fmax4(float4 a, float4 b) {
    a.x = fmaxf(a.x, b.x); a.y = fmaxf(a.y, b.y);
    a.z = fmaxf(a.z, b.z); a.w = fmaxf(a.w, b.w);
    return a;
}

// One warp per node. 4 chains; half-warp hw chases chains {2hw, 2hw+1}
// interleaved (independent link loads -> MLP 2, serial depth ~deg/4).
__global__ void k_aggregate(const float* __restrict__ h,
                            float* __restrict__ out, int n) {
    int warp = (blockIdx.x * blockDim.x + threadIdx.x) >> 5;
    int lane = threadIdx.x & 31;
    if (warp >= n) return;

    int hw = lane >> 4;
    int fl = lane & 15;

    const int4* heads4 = reinterpret_cast<const int4*>(g_head);
    int4 heads = __ldg(&heads4[warp]);                    // broadcast LDG.128

    int e0 = (hw == 0) ? heads.x : heads.z;
    int e1 = (hw == 0) ? heads.y : heads.w;
    bool isolated = (heads.x < 0) & (heads.y < 0) & (heads.z < 0) & (heads.w < 0);

    const float NEG_INF = __int_as_float(0xff800000);
    float4 acc = make_float4(NEG_INF, NEG_INF, NEG_INF, NEG_INF);

    const float4* __restrict__ h4 = reinterpret_cast<const float4*>(h);

    while (e0 >= 0 || e1 >= 0) {
        int2 l0, l1;
        bool a0 = (e0 >= 0), a1 = (e1 >= 0);
        if (a0) l0 = __ldg(&g_link[e0]);                  // independent pair:
        if (a1) l1 = __ldg(&g_link[e1]);                  // both in flight
        if (a0) {
            float4 v = __ldg(&h4[l0.y * F4_PER_ROW + fl]);
            acc = fmax4(acc, v);
            e0 = l0.x;
        }
        if (a1) {
            float4 v = __ldg(&h4[l1.y * F4_PER_ROW + fl]);
            acc = fmax4(acc, v);
            e1 = l1.x;
        }
    }

    // combine the two half-warps (same feature chunk at lane and lane^16)
    acc.x = fmaxf(acc.x, __shfl_xor_sync(0xffffffffu, acc.x, 16));
    acc.y = fmaxf(acc.y, __shfl_xor_sync(0xffffffffu, acc.y, 16));
    acc.z = fmaxf(acc.z, __shfl_xor_sync(0xffffffffu, acc.z, 16));
    acc.w = fmaxf(acc.w, __shfl_xor_sync(0xffffffffu, acc.w, 16));

    if (isolated) acc = make_float4(0.f, 0.f, 0.f, 0.f);

    if (lane < 16)
        reinterpret_cast<float4*>(out)[warp * F4_PER_ROW + fl] = acc;
}

// -------- launch: memset + 2 kernels --------
extern "C" void kernel_launch(void* const* d_in, const int* in_sizes, int n_in,
                              void* d_out, int out_size) {
    const float* h = (const float*)d_in[0];
    const int* edge_index = (const int*)d_in[1];
    float* out = (float*)d_out;

    const int N = in_sizes[0] / D_FEAT;      // 100000
    const int E = in_sizes[1] / 2;           // 1600000

    void* p_head = nullptr;
    cudaGetSymbolAddress(&p_head, g_head);
    cudaMemsetAsync(p_head, 0xFF, (size_t)NCHAIN * N * sizeof(int));

    const int T = 256;
    k_build<<<(E + T - 1) / T, T>>>(edge_index, E);

    int blocks = (N * 32 + T - 1) / T;       // 12500
    k_aggregate<<<blocks, T>>>(h, out, N);
}